// round 1
// baseline (speedup 1.0000x reference)
#include <cuda_runtime.h>
#include <math_constants.h>

#define NROI   1500
#define NCLS   80          // foreground classes 1..80
#define NTOT   (NROI*NCLS) // 120000
#define SCORE_THRESH 0.05f
#define NMS_THRESH   0.5f
#define MAX_DET 100

// ---------------- scratch (device globals; no allocation) ----------------
__device__ float g_boxes[NTOT*4];   // [c][i][4] decoded+clipped boxes (orig roi index)
__device__ int   g_order[NTOT];     // [c][j] -> original roi index (sorted by score desc)
__device__ float g_sscore[NTOT];    // [c][j] sorted scores
__device__ unsigned char g_keep[NTOT]; // keep flag in sorted-position space (pre-topk)
__device__ float g_ksc[NTOT];       // compacted kept scores
__device__ int   g_kcount;
__device__ float g_kth;
__device__ int   g_filter;

// ---------------- kernel 1: decode boxes + reset scratch ----------------
__global__ __launch_bounds__(256) void k_decode(const float* __restrict__ rois,
                                                const float* __restrict__ delta,
                                                const float* __restrict__ iminfo) {
    int t = blockIdx.x*blockDim.x + threadIdx.x;
    if (t == 0) g_kcount = 0;
    if (t >= NTOT) return;
    g_keep[t] = 0;

    int c   = t / NROI;       // 0..79
    int i   = t % NROI;
    int cls = c + 1;          // 1..80

    float x1 = rois[i*5+1], y1 = rois[i*5+2], x2 = rois[i*5+3], y2 = rois[i*5+4];
    float w  = x2 - x1 + 1.0f;
    float h  = y2 - y1 + 1.0f;
    float cx = x1 + 0.5f*w;
    float cy = y1 + 0.5f*h;

    const float4 d4 = *reinterpret_cast<const float4*>(delta + (size_t)i*(4*81) + 4*cls);
    float dx = d4.x / 10.0f;
    float dy = d4.y / 10.0f;
    float dw = d4.z / 5.0f;
    float dh = d4.w / 5.0f;

    float pcx = cx + w*dx;
    float pcy = cy + h*dy;
    float pw  = w * expf(dw);
    float ph  = h * expf(dh);

    float H = iminfo[0], W = iminfo[1];
    float lx = W - 1.0f, ly = H - 1.0f;

    float bx1 = fminf(fmaxf(pcx - 0.5f*pw,        0.0f), lx);
    float by1 = fminf(fmaxf(pcy - 0.5f*ph,        0.0f), ly);
    float bx2 = fminf(fmaxf(pcx + 0.5f*pw - 1.0f, 0.0f), lx);
    float by2 = fminf(fmaxf(pcy + 0.5f*ph - 1.0f, 0.0f), ly);

    reinterpret_cast<float4*>(g_boxes)[t] = make_float4(bx1, by1, bx2, by2);
}

// ---------------- kernel 2: per-class stable descending sort (bitonic) ----------------
__global__ __launch_bounds__(1024) void k_sort(const float* __restrict__ prob) {
    const int c = blockIdx.x;       // class slot 0..79 -> class c+1
    const int cls = c + 1;
    const int tid = threadIdx.x;    // 1024 threads
    __shared__ unsigned long long sk[2048];

    for (int j = tid; j < 2048; j += 1024) {
        unsigned long long key = 0ull;   // padding sorts last
        if (j < NROI) {
            float s = prob[(size_t)j*81 + cls];
            unsigned int b = __float_as_uint(s);
            unsigned int u = (b & 0x80000000u) ? ~b : (b | 0x80000000u); // order-preserving
            key = ((unsigned long long)u << 32) | (unsigned long long)(0xFFFFFFFFu - (unsigned)j);
        }
        sk[j] = key;
    }
    __syncthreads();

    // descending bitonic sort of 2048 elements
    for (int size = 2; size <= 2048; size <<= 1) {
        for (int stride = size >> 1; stride > 0; stride >>= 1) {
            int pos = 2*tid - (tid & (stride - 1));
            bool desc = (pos & size) == 0;
            unsigned long long a = sk[pos], b = sk[pos + stride];
            if ((a < b) == desc) { sk[pos] = b; sk[pos + stride] = a; }
            __syncthreads();
        }
    }

    for (int j = tid; j < NROI; j += 1024) {
        unsigned long long key = sk[j];
        int idx = (int)(0xFFFFFFFFu - (unsigned int)(key & 0xFFFFFFFFull));
        g_order[c*NROI + j]  = idx;
        g_sscore[c*NROI + j] = prob[(size_t)idx*81 + cls];
    }
}

// ---------------- kernel 3: per-class greedy NMS on valid prefix ----------------
__global__ __launch_bounds__(256) void k_nms() {
    const int c = blockIdx.x;
    const int tid = threadIdx.x;
    const int base = c*NROI;

    __shared__ float sx1[NROI], sy1[NROI], sx2[NROI], sy2[NROI], sar[NROI], ssc[NROI];
    __shared__ unsigned char sup[NROI];
    __shared__ int s_nv;
    if (tid == 0) s_nv = 0;
    __syncthreads();

    int lc = 0;
    for (int j = tid; j < NROI; j += 256) {
        int idx = g_order[base + j];
        float4 b = reinterpret_cast<const float4*>(g_boxes)[base + idx];
        sx1[j] = b.x; sy1[j] = b.y; sx2[j] = b.z; sy2[j] = b.w;
        sar[j] = (b.z - b.x + 1.0f) * (b.w - b.y + 1.0f);
        float s = g_sscore[base + j];
        ssc[j] = s;
        sup[j] = 0;
        if (s > SCORE_THRESH) lc++;
    }
    atomicAdd(&s_nv, lc);
    __syncthreads();
    const int nv = s_nv;   // valid boxes form a prefix (sorted by score desc)

    for (int i = 0; i < nv; ++i) {
        if (!sup[i]) {                   // uniform: shared, synced each iter
            if (tid == 0) {
                g_keep[base + i] = 1;
                int p = atomicAdd(&g_kcount, 1);
                g_ksc[p] = ssc[i];
            }
            float x1 = sx1[i], y1 = sy1[i], x2 = sx2[i], y2 = sy2[i], ai = sar[i];
            for (int j = i + 1 + tid; j < nv; j += 256) {
                if (sup[j]) continue;
                float iw = fminf(x2, sx2[j]) - fmaxf(x1, sx1[j]) + 1.0f;
                float ih = fminf(y2, sy2[j]) - fmaxf(y1, sy1[j]) + 1.0f;
                iw = fmaxf(iw, 0.0f);
                ih = fmaxf(ih, 0.0f);
                float inter = iw * ih;
                float iou = inter / (ai + sar[j] - inter);
                if (iou > NMS_THRESH) sup[j] = 1;
            }
        }
        __syncthreads();
    }
}

// ---------------- kernel 4: value of 100th-largest kept score ----------------
__global__ __launch_bounds__(256) void k_topk() {
    const int tid = threadIdx.x;
    const int count = g_kcount;
    __shared__ float rv[256];
    __shared__ int   ri[256];

    if (count <= MAX_DET) {
        if (tid == 0) { g_filter = 0; g_kth = -CUDART_INF_F; }
        return;
    }

    float kth = -CUDART_INF_F;
    for (int iter = 0; iter < MAX_DET; ++iter) {
        float bv = -CUDART_INF_F;
        int   bi = 0x7FFFFFFF;
        for (int j = tid; j < count; j += 256) {
            float v = g_ksc[j];
            if (v > bv || (v == bv && j < bi)) { bv = v; bi = j; }
        }
        rv[tid] = bv; ri[tid] = bi;
        __syncthreads();
        for (int s = 128; s > 0; s >>= 1) {
            if (tid < s) {
                if (rv[tid+s] > rv[tid] || (rv[tid+s] == rv[tid] && ri[tid+s] < ri[tid])) {
                    rv[tid] = rv[tid+s]; ri[tid] = ri[tid+s];
                }
            }
            __syncthreads();
        }
        if (tid == 0) g_ksc[ri[0]] = -CUDART_INF_F;   // consume one instance
        kth = rv[0];
        __syncthreads();
    }
    if (tid == 0) { g_filter = 1; g_kth = kth; }
}

// ---------------- kernel 5: write output ----------------
// layout (float32): dets[120000*6] | cls_idx[120000] | keep[120000]
__global__ __launch_bounds__(256) void k_out(float* __restrict__ out) {
    int r = blockIdx.x*blockDim.x + threadIdx.x;
    if (r >= NTOT) return;
    int c = r / NROI;

    float s = g_sscore[r];
    bool kp = g_keep[r] && (!g_filter || s >= g_kth);

    float4 b = make_float4(0.f, 0.f, 0.f, 0.f);
    if (kp) {
        int idx = g_order[r];
        b = reinterpret_cast<const float4*>(g_boxes)[c*NROI + idx];
    }
    float* d = out + (size_t)r*6;
    d[0] = 0.0f;
    d[1] = kp ? b.x : 0.0f;
    d[2] = kp ? b.y : 0.0f;
    d[3] = kp ? b.z : 0.0f;
    d[4] = kp ? b.w : 0.0f;
    d[5] = kp ? s   : 0.0f;

    out[NTOT*6 + r]     = (float)(c + 1);     // cls_idx
    out[NTOT*6 + NTOT + r] = kp ? 1.0f : 0.0f; // keep
}

extern "C" void kernel_launch(void* const* d_in, const int* in_sizes, int n_in,
                              void* d_out, int out_size) {
    const float* rois   = (const float*)d_in[0];
    const float* delta  = (const float*)d_in[1];
    const float* prob   = (const float*)d_in[2];
    const float* iminfo = (const float*)d_in[3];
    float* out = (float*)d_out;

    k_decode<<<(NTOT + 255)/256, 256>>>(rois, delta, iminfo);
    k_sort<<<NCLS, 1024>>>(prob);
    k_nms<<<NCLS, 256>>>();
    k_topk<<<1, 256>>>();
    k_out<<<(NTOT + 255)/256, 256>>>(out);
}

// round 2
// speedup vs baseline: 2.0528x; 2.0528x over previous
#include <cuda_runtime.h>
#include <math_constants.h>

#define NROI   1500
#define NCLS   80          // foreground classes 1..80
#define NTOT   (NROI*NCLS) // 120000
#define SCORE_THRESH 0.05f
#define NMS_THRESH   0.5f
#define MAX_DET 100

// ---------------- scratch (device globals; no allocation) ----------------
__device__ float g_boxes[NTOT*4];   // [c][i][4] decoded+clipped boxes (orig roi index)
__device__ int   g_order[NTOT];     // [c][j] -> original roi index (sorted by score desc)
__device__ float g_sscore[NTOT];    // [c][j] sorted scores
__device__ unsigned char g_keep[NTOT]; // keep flag in sorted-position space (pre-topk)
__device__ float g_ksc[NTOT];       // compacted kept scores
__device__ int   g_kcount;
__device__ float g_kth;
__device__ int   g_filter;

// ---------------- kernel 1: decode boxes + reset scratch ----------------
__global__ __launch_bounds__(256) void k_decode(const float* __restrict__ rois,
                                                const float* __restrict__ delta,
                                                const float* __restrict__ iminfo) {
    int t = blockIdx.x*blockDim.x + threadIdx.x;
    if (t == 0) g_kcount = 0;
    if (t >= NTOT) return;
    g_keep[t] = 0;

    int c   = t / NROI;       // 0..79
    int i   = t % NROI;
    int cls = c + 1;          // 1..80

    float x1 = rois[i*5+1], y1 = rois[i*5+2], x2 = rois[i*5+3], y2 = rois[i*5+4];
    float w  = x2 - x1 + 1.0f;
    float h  = y2 - y1 + 1.0f;
    float cx = x1 + 0.5f*w;
    float cy = y1 + 0.5f*h;

    const float4 d4 = *reinterpret_cast<const float4*>(delta + (size_t)i*(4*81) + 4*cls);
    float dx = d4.x / 10.0f;
    float dy = d4.y / 10.0f;
    float dw = d4.z / 5.0f;
    float dh = d4.w / 5.0f;

    float pcx = cx + w*dx;
    float pcy = cy + h*dy;
    float pw  = w * expf(dw);
    float ph  = h * expf(dh);

    float H = iminfo[0], W = iminfo[1];
    float lx = W - 1.0f, ly = H - 1.0f;

    float bx1 = fminf(fmaxf(pcx - 0.5f*pw,        0.0f), lx);
    float by1 = fminf(fmaxf(pcy - 0.5f*ph,        0.0f), ly);
    float bx2 = fminf(fmaxf(pcx + 0.5f*pw - 1.0f, 0.0f), lx);
    float by2 = fminf(fmaxf(pcy + 0.5f*ph - 1.0f, 0.0f), ly);

    reinterpret_cast<float4*>(g_boxes)[t] = make_float4(bx1, by1, bx2, by2);
}

// ---------------- kernel 2: per-class stable descending sort (bitonic) ----------------
__global__ __launch_bounds__(1024) void k_sort(const float* __restrict__ prob) {
    const int c = blockIdx.x;       // class slot 0..79 -> class c+1
    const int cls = c + 1;
    const int tid = threadIdx.x;    // 1024 threads
    __shared__ unsigned long long sk[2048];

    for (int j = tid; j < 2048; j += 1024) {
        unsigned long long key = 0ull;   // padding sorts last
        if (j < NROI) {
            float s = prob[(size_t)j*81 + cls];
            unsigned int b = __float_as_uint(s);
            unsigned int u = (b & 0x80000000u) ? ~b : (b | 0x80000000u); // order-preserving
            key = ((unsigned long long)u << 32) | (unsigned long long)(0xFFFFFFFFu - (unsigned)j);
        }
        sk[j] = key;
    }
    __syncthreads();

    // descending bitonic sort of 2048 elements
    for (int size = 2; size <= 2048; size <<= 1) {
        for (int stride = size >> 1; stride > 0; stride >>= 1) {
            int pos = 2*tid - (tid & (stride - 1));
            bool desc = (pos & size) == 0;
            unsigned long long a = sk[pos], b = sk[pos + stride];
            if ((a < b) == desc) { sk[pos] = b; sk[pos + stride] = a; }
            __syncthreads();
        }
    }

    for (int j = tid; j < NROI; j += 1024) {
        unsigned long long key = sk[j];
        int idx = (int)(0xFFFFFFFFu - (unsigned int)(key & 0xFFFFFFFFull));
        g_order[c*NROI + j]  = idx;
        g_sscore[c*NROI + j] = prob[(size_t)idx*81 + cls];
    }
}

// ---------------- kernel 3: per-class greedy NMS on valid prefix ----------------
__global__ __launch_bounds__(256) void k_nms() {
    const int c = blockIdx.x;
    const int tid = threadIdx.x;
    const int base = c*NROI;

    __shared__ float sx1[NROI], sy1[NROI], sx2[NROI], sy2[NROI], sar[NROI], ssc[NROI];
    __shared__ unsigned char sup[NROI];
    __shared__ int s_nv;
    if (tid == 0) s_nv = 0;
    __syncthreads();

    int lc = 0;
    for (int j = tid; j < NROI; j += 256) {
        int idx = g_order[base + j];
        float4 b = reinterpret_cast<const float4*>(g_boxes)[base + idx];
        sx1[j] = b.x; sy1[j] = b.y; sx2[j] = b.z; sy2[j] = b.w;
        sar[j] = (b.z - b.x + 1.0f) * (b.w - b.y + 1.0f);
        float s = g_sscore[base + j];
        ssc[j] = s;
        sup[j] = 0;
        if (s > SCORE_THRESH) lc++;
    }
    atomicAdd(&s_nv, lc);
    __syncthreads();
    const int nv = s_nv;   // valid boxes form a prefix (sorted by score desc)

    int i = 0;
    while (i < nv) {
        // invariant: sup[i] == 0 here (loop advances past suppressed rows)
        if (tid == 0) {
            g_keep[base + i] = 1;
            int p = atomicAdd(&g_kcount, 1);
            g_ksc[p] = ssc[i];
        }
        float x1 = sx1[i], y1 = sy1[i], x2 = sx2[i], y2 = sy2[i], ai = sar[i];
        for (int j = i + 1 + tid; j < nv; j += 256) {
            if (sup[j]) continue;
            float iw = fminf(x2, sx2[j]) - fmaxf(x1, sx1[j]) + 1.0f;
            float ih = fminf(y2, sy2[j]) - fmaxf(y1, sy1[j]) + 1.0f;
            iw = fmaxf(iw, 0.0f);
            ih = fmaxf(ih, 0.0f);
            float inter = iw * ih;
            float iou = inter / (ai + sar[j] - inter);
            if (iou > NMS_THRESH) sup[j] = 1;
        }
        __syncthreads();
        // advance past suppressed rows without per-row barriers.
        // sup[i+1..] is stable now (all writes fenced by the barrier above);
        // every thread computes the same next i, reads only -> race-free.
        ++i;
        while (i < nv && sup[i]) ++i;
    }
}

// ---------------- kernel 4: radix-select the 100th-largest kept score ----------------
__global__ __launch_bounds__(256) void k_topk() {
    const int tid = threadIdx.x;
    const int count = g_kcount;

    if (count <= MAX_DET) {
        if (tid == 0) { g_filter = 0; g_kth = -CUDART_INF_F; }
        return;
    }

    __shared__ int hist[256];
    __shared__ unsigned int s_prefix;
    __shared__ int s_need;
    if (tid == 0) { s_prefix = 0u; s_need = MAX_DET; }
    __syncthreads();

    #pragma unroll
    for (int level = 0; level < 4; ++level) {
        const int shift = 24 - 8*level;
        const unsigned int dmask = (level == 0) ? 0u : (0xFFFFFFFFu << (shift + 8));
        hist[tid] = 0;
        __syncthreads();
        const unsigned int pfx = s_prefix;
        for (int j = tid; j < count; j += 256) {
            unsigned int b = __float_as_uint(g_ksc[j]);
            unsigned int u = (b & 0x80000000u) ? ~b : (b | 0x80000000u); // monotone key
            if ((u & dmask) == pfx)
                atomicAdd(&hist[(u >> shift) & 0xFFu], 1);
        }
        __syncthreads();
        if (tid == 0) {
            int need = s_need;
            unsigned int chosen = 0;
            for (int b = 255; b >= 0; --b) {
                if (need <= hist[b]) { chosen = (unsigned int)b; break; }
                need -= hist[b];
            }
            s_prefix = pfx | (chosen << shift);
            s_need = need;
        }
        __syncthreads();
    }

    if (tid == 0) {
        unsigned int u = s_prefix;   // exact key of the MAX_DET-th largest
        unsigned int b = (u & 0x80000000u) ? (u & 0x7FFFFFFFu) : ~u;
        g_kth = __uint_as_float(b);
        g_filter = 1;
    }
}

// ---------------- kernel 5: write output ----------------
// layout (float32): dets[120000*6] | cls_idx[120000] | keep[120000]
__global__ __launch_bounds__(256) void k_out(float* __restrict__ out) {
    int r = blockIdx.x*blockDim.x + threadIdx.x;
    if (r >= NTOT) return;
    int c = r / NROI;

    float s = g_sscore[r];
    bool kp = g_keep[r] && (!g_filter || s >= g_kth);

    float4 b = make_float4(0.f, 0.f, 0.f, 0.f);
    if (kp) {
        int idx = g_order[r];
        b = reinterpret_cast<const float4*>(g_boxes)[c*NROI + idx];
    }
    float* d = out + (size_t)r*6;
    d[0] = 0.0f;
    d[1] = kp ? b.x : 0.0f;
    d[2] = kp ? b.y : 0.0f;
    d[3] = kp ? b.z : 0.0f;
    d[4] = kp ? b.w : 0.0f;
    d[5] = kp ? s   : 0.0f;

    out[NTOT*6 + r]        = (float)(c + 1);   // cls_idx
    out[NTOT*6 + NTOT + r] = kp ? 1.0f : 0.0f; // keep
}

extern "C" void kernel_launch(void* const* d_in, const int* in_sizes, int n_in,
                              void* d_out, int out_size) {
    const float* rois   = (const float*)d_in[0];
    const float* delta  = (const float*)d_in[1];
    const float* prob   = (const float*)d_in[2];
    const float* iminfo = (const float*)d_in[3];
    float* out = (float*)d_out;

    k_decode<<<(NTOT + 255)/256, 256>>>(rois, delta, iminfo);
    k_sort<<<NCLS, 1024>>>(prob);
    k_nms<<<NCLS, 256>>>();
    k_topk<<<1, 256>>>();
    k_out<<<(NTOT + 255)/256, 256>>>(out);
}

// round 3
// speedup vs baseline: 4.0346x; 1.9654x over previous
#include <cuda_runtime.h>
#include <math_constants.h>

#define NROI   1500
#define NCLS   80          // foreground classes 1..80
#define NTOT   (NROI*NCLS) // 120000
#define SCORE_THRESH 0.05f
#define NMS_THRESH   0.5f
#define MAX_DET 100
#define CAP    1504        // max valid per class (<= NROI), padded
#define MASK_CAP 512       // bitmask NMS path supported up to this nv

// ---------------- scratch (device globals; no allocation) ----------------
__device__ float g_ksc[NTOT];      // compacted kept scores
__device__ float g_list[NTOT*8];   // kept entries: {s, c, j, x1, y1, x2, y2, 0}
__device__ int   g_kcount;
__device__ float g_kth;
__device__ int   g_filter;

__device__ __forceinline__ unsigned int mono_key(float s) {
    unsigned int b = __float_as_uint(s);
    return (b & 0x80000000u) ? ~b : (b | 0x80000000u);
}
__device__ __forceinline__ float inv_mono(unsigned int u) {
    unsigned int b = (u & 0x80000000u) ? (u & 0x7FFFFFFFu) : ~u;
    return __uint_as_float(b);
}

// ---------------- kernel 1: fill output + reset counters ----------------
// layout (float32): dets[NTOT*6] | cls_idx[NTOT] | keep[NTOT]
__global__ __launch_bounds__(512) void k_fill(float* __restrict__ out) {
    int q = blockIdx.x*blockDim.x + threadIdx.x;   // float4 index
    if (q == 0) g_kcount = 0;
    if (q >= (NTOT*8)/4) return;
    if (q < (NTOT*6)/4) {                        // dets: zeros
        reinterpret_cast<float4*>(out)[q] = make_float4(0.f,0.f,0.f,0.f);
    } else if (q < (NTOT*7)/4) {                 // cls_idx: c+1
        int r0 = q*4 - NTOT*6;
        float4 v;
        v.x = (float)((r0+0)/NROI + 1);
        v.y = (float)((r0+1)/NROI + 1);
        v.z = (float)((r0+2)/NROI + 1);
        v.w = (float)((r0+3)/NROI + 1);
        reinterpret_cast<float4*>(out)[q] = v;
    } else {                                     // keep: zeros
        reinterpret_cast<float4*>(out)[q] = make_float4(0.f,0.f,0.f,0.f);
    }
}

// ---------------- kernel 2: per-class compact+sort+decode+NMS (fused) ----------------
struct SMem {
    unsigned long long skey[2048];
    float sx1[CAP], sy1[CAP], sx2[CAP], sy2[CAP], sar[CAP], ssc[CAP];
    int   sidx[CAP];
    unsigned long long smask[MASK_CAP*8];  // also reused as sup[] bytes in fallback
    unsigned long long skeep[24];
    int   cnt;
};

__global__ __launch_bounds__(256) void k_main(const float* __restrict__ rois,
                                              const float* __restrict__ delta,
                                              const float* __restrict__ prob,
                                              const float* __restrict__ iminfo) {
    extern __shared__ char smem_raw[];
    SMem& sm = *reinterpret_cast<SMem*>(smem_raw);
    const int c   = blockIdx.x;
    const int cls = c + 1;
    const int tid = threadIdx.x;

    if (tid == 0) sm.cnt = 0;
    __syncthreads();

    // ---- compact valid entries as (score,idx) keys ----
    for (int j = tid; j < NROI; j += 256) {
        float s = prob[(size_t)j*81 + cls];
        if (s > SCORE_THRESH) {
            int p = atomicAdd(&sm.cnt, 1);
            sm.skey[p] = ((unsigned long long)mono_key(s) << 32)
                       | (unsigned long long)(0xFFFFFFFFu - (unsigned)j);
        }
    }
    __syncthreads();
    const int nv = sm.cnt;
    if (nv == 0) return;

    // ---- bitonic sort descending over m = next pow2 >= nv ----
    int m = 1; while (m < nv) m <<= 1;
    for (int j = nv + tid; j < m; j += 256) sm.skey[j] = 0ull; // pads last
    __syncthreads();
    for (int size = 2; size <= m; size <<= 1) {
        for (int stride = size >> 1; stride > 0; stride >>= 1) {
            for (int t = tid; t < (m >> 1); t += 256) {
                int pos = 2*t - (t & (stride - 1));
                bool desc = (pos & size) == 0;
                unsigned long long a = sm.skey[pos], b = sm.skey[pos + stride];
                if ((a < b) == desc) { sm.skey[pos] = b; sm.skey[pos + stride] = a; }
            }
            __syncthreads();
        }
    }

    // ---- decode boxes for the sorted valid prefix ----
    const float H = iminfo[0], W = iminfo[1];
    const float lx = W - 1.0f, ly = H - 1.0f;
    for (int j = tid; j < nv; j += 256) {
        unsigned long long k = sm.skey[j];
        int idx = (int)(0xFFFFFFFFu - (unsigned int)(k & 0xFFFFFFFFull));
        float s = inv_mono((unsigned int)(k >> 32));

        float x1 = rois[idx*5+1], y1 = rois[idx*5+2];
        float x2 = rois[idx*5+3], y2 = rois[idx*5+4];
        float w  = x2 - x1 + 1.0f;
        float h  = y2 - y1 + 1.0f;
        float cx = x1 + 0.5f*w;
        float cy = y1 + 0.5f*h;

        const float4 d4 = *reinterpret_cast<const float4*>(delta + (size_t)idx*(4*81) + 4*cls);
        float dx = d4.x / 10.0f, dy = d4.y / 10.0f;
        float dw = d4.z / 5.0f,  dh = d4.w / 5.0f;

        float pcx = cx + w*dx;
        float pcy = cy + h*dy;
        float pw  = w * expf(dw);
        float ph  = h * expf(dh);

        float bx1 = fminf(fmaxf(pcx - 0.5f*pw,        0.0f), lx);
        float by1 = fminf(fmaxf(pcy - 0.5f*ph,        0.0f), ly);
        float bx2 = fminf(fmaxf(pcx + 0.5f*pw - 1.0f, 0.0f), lx);
        float by2 = fminf(fmaxf(pcy + 0.5f*ph - 1.0f, 0.0f), ly);

        sm.sx1[j] = bx1; sm.sy1[j] = by1; sm.sx2[j] = bx2; sm.sy2[j] = by2;
        sm.sar[j] = (bx2 - bx1 + 1.0f) * (by2 - by1 + 1.0f);
        sm.ssc[j] = s;
        sm.sidx[j] = idx;
    }
    __syncthreads();

    // ---- NMS ----
    if (nv <= MASK_CAP) {
        // bitmask path: parallel pairwise IoU, serial scan = pure bit ops
        const int MW = (nv + 63) >> 6;
        for (int i = tid; i < nv; i += 256) {
            float x1 = sm.sx1[i], y1 = sm.sy1[i], x2 = sm.sx2[i], y2 = sm.sy2[i];
            float ai = sm.sar[i];
            unsigned long long row[8];
            #pragma unroll
            for (int w = 0; w < 8; w++) row[w] = 0ull;
            for (int j = i + 1; j < nv; j++) {
                float iw = fminf(x2, sm.sx2[j]) - fmaxf(x1, sm.sx1[j]) + 1.0f;
                float ih = fminf(y2, sm.sy2[j]) - fmaxf(y1, sm.sy1[j]) + 1.0f;
                iw = fmaxf(iw, 0.0f);
                ih = fmaxf(ih, 0.0f);
                float inter = iw * ih;
                float iou = inter / (ai + sm.sar[j] - inter);
                if (iou > NMS_THRESH) row[j >> 6] |= (1ull << (j & 63));
            }
            #pragma unroll
            for (int w = 0; w < 8; w++) sm.smask[i*8 + w] = row[w];
        }
        __syncthreads();
        if (tid == 0) {
            unsigned long long keepw[8], supw[8];
            #pragma unroll
            for (int w = 0; w < 8; w++) { keepw[w] = 0ull; supw[w] = 0ull; }
            for (int i = 0; i < nv; i++) {
                if (!((supw[i >> 6] >> (i & 63)) & 1ull)) {
                    keepw[i >> 6] |= (1ull << (i & 63));
                    for (int w = (i >> 6); w < MW; w++) supw[w] |= sm.smask[i*8 + w];
                }
            }
            for (int w = 0; w < MW; w++) sm.skeep[w] = keepw[w];
        }
        __syncthreads();
    } else {
        // fallback: sequential greedy sweep (rare; nv > 512)
        unsigned char* sup = reinterpret_cast<unsigned char*>(sm.smask);
        for (int j = tid; j < nv; j += 256) sup[j] = 0;
        if (tid < 24) sm.skeep[tid] = 0ull;
        __syncthreads();
        int i = 0;
        while (i < nv) {
            if (tid == 0) sm.skeep[i >> 6] |= (1ull << (i & 63));
            float x1 = sm.sx1[i], y1 = sm.sy1[i], x2 = sm.sx2[i], y2 = sm.sy2[i];
            float ai = sm.sar[i];
            for (int j = i + 1 + tid; j < nv; j += 256) {
                if (sup[j]) continue;
                float iw = fminf(x2, sm.sx2[j]) - fmaxf(x1, sm.sx1[j]) + 1.0f;
                float ih = fminf(y2, sm.sy2[j]) - fmaxf(y1, sm.sy1[j]) + 1.0f;
                iw = fmaxf(iw, 0.0f);
                ih = fmaxf(ih, 0.0f);
                float inter = iw * ih;
                float iou = inter / (ai + sm.sar[j] - inter);
                if (iou > NMS_THRESH) sup[j] = 1;
            }
            __syncthreads();
            ++i;
            while (i < nv && sup[i]) ++i;
        }
    }

    // ---- append kept entries to global list ----
    for (int j = tid; j < nv; j += 256) {
        if ((sm.skeep[j >> 6] >> (j & 63)) & 1ull) {
            int p = atomicAdd(&g_kcount, 1);
            g_ksc[p] = sm.ssc[j];
            float4* L = reinterpret_cast<float4*>(g_list + (size_t)p*8);
            L[0] = make_float4(sm.ssc[j], (float)c, (float)j, sm.sx1[j]);
            L[1] = make_float4(sm.sy1[j], sm.sx2[j], sm.sy2[j], 0.f);
        }
    }
}

// ---------------- kernel 3: radix-select the 100th-largest kept score ----------------
__global__ __launch_bounds__(1024) void k_topk() {
    const int tid = threadIdx.x;
    const int count = g_kcount;

    if (count <= MAX_DET) {
        if (tid == 0) { g_filter = 0; g_kth = -CUDART_INF_F; }
        return;
    }

    __shared__ int hist[256];
    __shared__ int sfx[256];
    __shared__ unsigned int s_prefix;
    __shared__ int s_need;
    if (tid == 0) { s_prefix = 0u; s_need = MAX_DET; }
    __syncthreads();

    #pragma unroll
    for (int level = 0; level < 4; ++level) {
        const int shift = 24 - 8*level;
        const unsigned int dmask = (level == 0) ? 0u : (0xFFFFFFFFu << (shift + 8));
        if (tid < 256) hist[tid] = 0;
        __syncthreads();
        const unsigned int pfx = s_prefix;
        for (int j = tid; j < count; j += 1024) {
            unsigned int u = mono_key(g_ksc[j]);       // L1-hot after level 0
            if ((u & dmask) == pfx)
                atomicAdd(&hist[(u >> shift) & 0xFFu], 1);
        }
        __syncthreads();
        // suffix sum: sfx[b] = sum_{j>=b} hist[j]  (parallel scan)
        if (tid < 256) sfx[tid] = hist[tid];
        __syncthreads();
        for (int off = 1; off < 256; off <<= 1) {
            int v = 0;
            if (tid < 256) { v = sfx[tid]; if (tid + off < 256) v += sfx[tid + off]; }
            __syncthreads();
            if (tid < 256) sfx[tid] = v;
            __syncthreads();
        }
        if (tid < 256) {
            int need = s_need;
            int hi = (tid == 255) ? 0 : sfx[tid + 1];
            if (sfx[tid] >= need && hi < need) {       // unique chosen bin
                s_prefix = pfx | ((unsigned int)tid << shift);
                s_need   = need - hi;
            }
        }
        __syncthreads();
    }

    if (tid == 0) {
        g_kth = inv_mono(s_prefix);   // exact value of the MAX_DET-th largest
        g_filter = 1;
    }
}

// ---------------- kernel 4: scatter kept rows into the output ----------------
__global__ __launch_bounds__(1024) void k_scatter(float* __restrict__ out) {
    const int tid = threadIdx.x;
    const int count = g_kcount;
    const int filt = g_filter;
    const float kth = g_kth;

    for (int e = tid; e < count; e += 1024) {
        const float4 L0 = reinterpret_cast<const float4*>(g_list + (size_t)e*8)[0];
        const float4 L1 = reinterpret_cast<const float4*>(g_list + (size_t)e*8)[1];
        float s = L0.x;
        if (filt && !(s >= kth)) continue;
        int c = (int)L0.y;
        int j = (int)L0.z;
        int r = c*NROI + j;
        float* d = out + (size_t)r*6;
        d[0] = 0.0f;
        d[1] = L0.w;  // x1
        d[2] = L1.x;  // y1
        d[3] = L1.y;  // x2
        d[4] = L1.z;  // y2
        d[5] = s;
        out[NTOT*7 + r] = 1.0f;   // keep flag
    }
}

extern "C" void kernel_launch(void* const* d_in, const int* in_sizes, int n_in,
                              void* d_out, int out_size) {
    const float* rois   = (const float*)d_in[0];
    const float* delta  = (const float*)d_in[1];
    const float* prob   = (const float*)d_in[2];
    const float* iminfo = (const float*)d_in[3];
    float* out = (float*)d_out;

    static_assert(sizeof(SMem) < 100*1024, "smem budget");
    cudaFuncSetAttribute(k_main, cudaFuncAttributeMaxDynamicSharedMemorySize,
                         (int)sizeof(SMem));

    k_fill<<<((NTOT*8)/4 + 511)/512, 512>>>(out);
    k_main<<<NCLS, 256, sizeof(SMem)>>>(rois, delta, prob, iminfo);
    k_topk<<<1, 1024>>>();
    k_scatter<<<1, 1024>>>(out);
}

// round 4
// speedup vs baseline: 4.0682x; 1.0083x over previous
#include <cuda_runtime.h>
#include <math_constants.h>

#define NROI   1500
#define NCLS   80          // foreground classes 1..80
#define NTOT   (NROI*NCLS) // 120000
#define SCORE_THRESH 0.05f
#define NMS_THRESH   0.5f
#define MAX_DET 100
#define CAP    1504        // max valid per class (<= NROI), padded
#define MASK_CAP 512       // bitmask NMS path supported up to this nv

// Output float4 quads split across the NCLS blocks of k_main
#define QTOT   ((NTOT*8)/4)        // 240000
#define QPB    (QTOT/NCLS)         // 3000 per block

// ---------------- scratch (device globals; no allocation) ----------------
// g_kcount is zero-initialized at load and restored to 0 at the end of every
// k_final run -> every invocation (correctness, capture, replays) sees 0.
__device__ float g_ksc[NTOT];      // compacted kept scores
__device__ float g_list[NTOT*8];   // kept entries: {s, c, j, x1, y1, x2, y2, 0}
__device__ int   g_kcount;

__device__ __forceinline__ unsigned int mono_key(float s) {
    unsigned int b = __float_as_uint(s);
    return (b & 0x80000000u) ? ~b : (b | 0x80000000u);
}
__device__ __forceinline__ float inv_mono(unsigned int u) {
    unsigned int b = (u & 0x80000000u) ? (u & 0x7FFFFFFFu) : ~u;
    return __uint_as_float(b);
}

// ---------------- kernel 1: fill + per-class compact+sort+decode+NMS ----------------
struct SMem {
    unsigned long long skey[2048];
    float sx1[CAP], sy1[CAP], sx2[CAP], sy2[CAP], sar[CAP], ssc[CAP];
    unsigned long long smask[MASK_CAP*8];  // reused as sup[] bytes in fallback
    unsigned long long skeep[24];
    int   cnt;
};

__global__ __launch_bounds__(256) void k_main(const float* __restrict__ rois,
                                              const float* __restrict__ delta,
                                              const float* __restrict__ prob,
                                              const float* __restrict__ iminfo,
                                              float* __restrict__ out) {
    extern __shared__ char smem_raw[];
    SMem& sm = *reinterpret_cast<SMem*>(smem_raw);
    const int c   = blockIdx.x;
    const int cls = c + 1;
    const int tid = threadIdx.x;

    if (tid == 0) sm.cnt = 0;
    __syncthreads();

    // ---- fill this block's 1/NCLS slice of the output ----
    // layout (float32): dets[NTOT*6]=0 | cls_idx[NTOT]=class | keep[NTOT]=0
    {
        float4* o4 = reinterpret_cast<float4*>(out);
        const int q0 = c*QPB, q1 = q0 + QPB;
        for (int q = q0 + tid; q < q1; q += 256) {
            float4 v = make_float4(0.f,0.f,0.f,0.f);
            if (q >= (NTOT*6)/4 && q < (NTOT*7)/4) {
                int r0 = q*4 - NTOT*6;
                v.x = (float)((r0+0)/NROI + 1);
                v.y = (float)((r0+1)/NROI + 1);
                v.z = (float)((r0+2)/NROI + 1);
                v.w = (float)((r0+3)/NROI + 1);
            }
            o4[q] = v;
        }
    }

    // ---- compact valid entries as (score,idx) keys ----
    for (int j = tid; j < NROI; j += 256) {
        float s = prob[(size_t)j*81 + cls];
        if (s > SCORE_THRESH) {
            int p = atomicAdd(&sm.cnt, 1);
            sm.skey[p] = ((unsigned long long)mono_key(s) << 32)
                       | (unsigned long long)(0xFFFFFFFFu - (unsigned)j);
        }
    }
    __syncthreads();
    const int nv = sm.cnt;
    if (nv == 0) return;

    // ---- bitonic sort descending over m = next pow2 >= nv ----
    int m = 1; while (m < nv) m <<= 1;
    for (int j = nv + tid; j < m; j += 256) sm.skey[j] = 0ull; // pads last
    __syncthreads();
    for (int size = 2; size <= m; size <<= 1) {
        for (int stride = size >> 1; stride > 0; stride >>= 1) {
            for (int t = tid; t < (m >> 1); t += 256) {
                int pos = 2*t - (t & (stride - 1));
                bool desc = (pos & size) == 0;
                unsigned long long a = sm.skey[pos], b = sm.skey[pos + stride];
                if ((a < b) == desc) { sm.skey[pos] = b; sm.skey[pos + stride] = a; }
            }
            __syncthreads();
        }
    }

    // ---- decode boxes for the sorted valid prefix ----
    const float H = iminfo[0], W = iminfo[1];
    const float lx = W - 1.0f, ly = H - 1.0f;
    for (int j = tid; j < nv; j += 256) {
        unsigned long long k = sm.skey[j];
        int idx = (int)(0xFFFFFFFFu - (unsigned int)(k & 0xFFFFFFFFull));
        float s = inv_mono((unsigned int)(k >> 32));

        float x1 = rois[idx*5+1], y1 = rois[idx*5+2];
        float x2 = rois[idx*5+3], y2 = rois[idx*5+4];
        float w  = x2 - x1 + 1.0f;
        float h  = y2 - y1 + 1.0f;
        float cx = x1 + 0.5f*w;
        float cy = y1 + 0.5f*h;

        const float4 d4 = *reinterpret_cast<const float4*>(delta + (size_t)idx*(4*81) + 4*cls);
        float dx = d4.x / 10.0f, dy = d4.y / 10.0f;
        float dw = d4.z / 5.0f,  dh = d4.w / 5.0f;

        float pcx = cx + w*dx;
        float pcy = cy + h*dy;
        float pw  = w * expf(dw);
        float ph  = h * expf(dh);

        float bx1 = fminf(fmaxf(pcx - 0.5f*pw,        0.0f), lx);
        float by1 = fminf(fmaxf(pcy - 0.5f*ph,        0.0f), ly);
        float bx2 = fminf(fmaxf(pcx + 0.5f*pw - 1.0f, 0.0f), lx);
        float by2 = fminf(fmaxf(pcy + 0.5f*ph - 1.0f, 0.0f), ly);

        sm.sx1[j] = bx1; sm.sy1[j] = by1; sm.sx2[j] = bx2; sm.sy2[j] = by2;
        sm.sar[j] = (bx2 - bx1 + 1.0f) * (by2 - by1 + 1.0f);
        sm.ssc[j] = s;
    }
    __syncthreads();

    // ---- NMS ----
    if (nv <= MASK_CAP) {
        // bitmask path: parallel pairwise IoU, serial scan = pure bit ops
        const int MW = (nv + 63) >> 6;
        for (int i = tid; i < nv; i += 256) {
            float x1 = sm.sx1[i], y1 = sm.sy1[i], x2 = sm.sx2[i], y2 = sm.sy2[i];
            float ai = sm.sar[i];
            unsigned long long row[8];
            #pragma unroll
            for (int w = 0; w < 8; w++) row[w] = 0ull;
            for (int j = i + 1; j < nv; j++) {
                float iw = fminf(x2, sm.sx2[j]) - fmaxf(x1, sm.sx1[j]) + 1.0f;
                float ih = fminf(y2, sm.sy2[j]) - fmaxf(y1, sm.sy1[j]) + 1.0f;
                iw = fmaxf(iw, 0.0f);
                ih = fmaxf(ih, 0.0f);
                float inter = iw * ih;
                float iou = inter / (ai + sm.sar[j] - inter);
                if (iou > NMS_THRESH) row[j >> 6] |= (1ull << (j & 63));
            }
            #pragma unroll
            for (int w = 0; w < 8; w++) sm.smask[i*8 + w] = row[w];
        }
        __syncthreads();
        if (tid == 0) {
            unsigned long long keepw[8], supw[8];
            #pragma unroll
            for (int w = 0; w < 8; w++) { keepw[w] = 0ull; supw[w] = 0ull; }
            for (int i = 0; i < nv; i++) {
                if (!((supw[i >> 6] >> (i & 63)) & 1ull)) {
                    keepw[i >> 6] |= (1ull << (i & 63));
                    for (int w = (i >> 6); w < MW; w++) supw[w] |= sm.smask[i*8 + w];
                }
            }
            for (int w = 0; w < MW; w++) sm.skeep[w] = keepw[w];
        }
        __syncthreads();
    } else {
        // fallback: sequential greedy sweep (rare; nv > 512)
        unsigned char* sup = reinterpret_cast<unsigned char*>(sm.smask);
        for (int j = tid; j < nv; j += 256) sup[j] = 0;
        if (tid < 24) sm.skeep[tid] = 0ull;
        __syncthreads();
        int i = 0;
        while (i < nv) {
            if (tid == 0) sm.skeep[i >> 6] |= (1ull << (i & 63));
            float x1 = sm.sx1[i], y1 = sm.sy1[i], x2 = sm.sx2[i], y2 = sm.sy2[i];
            float ai = sm.sar[i];
            for (int j = i + 1 + tid; j < nv; j += 256) {
                if (sup[j]) continue;
                float iw = fminf(x2, sm.sx2[j]) - fmaxf(x1, sm.sx1[j]) + 1.0f;
                float ih = fminf(y2, sm.sy2[j]) - fmaxf(y1, sm.sy1[j]) + 1.0f;
                iw = fmaxf(iw, 0.0f);
                ih = fmaxf(ih, 0.0f);
                float inter = iw * ih;
                float iou = inter / (ai + sm.sar[j] - inter);
                if (iou > NMS_THRESH) sup[j] = 1;
            }
            __syncthreads();
            ++i;
            while (i < nv && sup[i]) ++i;
        }
    }

    // ---- append kept entries to global list ----
    for (int j = tid; j < nv; j += 256) {
        if ((sm.skeep[j >> 6] >> (j & 63)) & 1ull) {
            int p = atomicAdd(&g_kcount, 1);
            g_ksc[p] = sm.ssc[j];
            float4* L = reinterpret_cast<float4*>(g_list + (size_t)p*8);
            L[0] = make_float4(sm.ssc[j], (float)c, (float)j, sm.sx1[j]);
            L[1] = make_float4(sm.sy1[j], sm.sx2[j], sm.sy2[j], 0.f);
        }
    }
}

// ---------------- kernel 2: radix-select kth + scatter + reset ----------------
__global__ __launch_bounds__(1024) void k_final(float* __restrict__ out) {
    const int tid = threadIdx.x;
    const int count = g_kcount;

    __shared__ int hist[256];
    __shared__ int sfx[256];
    __shared__ unsigned int s_prefix;
    __shared__ int s_need;

    int   filt = 0;
    float kth  = -CUDART_INF_F;

    if (count > MAX_DET) {
        if (tid == 0) { s_prefix = 0u; s_need = MAX_DET; }
        __syncthreads();

        #pragma unroll
        for (int level = 0; level < 4; ++level) {
            const int shift = 24 - 8*level;
            const unsigned int dmask = (level == 0) ? 0u : (0xFFFFFFFFu << (shift + 8));
            if (tid < 256) hist[tid] = 0;
            __syncthreads();
            const unsigned int pfx = s_prefix;
            for (int j = tid; j < count; j += 1024) {
                unsigned int u = mono_key(g_ksc[j]);       // L1-hot after level 0
                if ((u & dmask) == pfx)
                    atomicAdd(&hist[(u >> shift) & 0xFFu], 1);
            }
            __syncthreads();
            // suffix sum: sfx[b] = sum_{j>=b} hist[j]
            if (tid < 256) sfx[tid] = hist[tid];
            __syncthreads();
            for (int off = 1; off < 256; off <<= 1) {
                int v = 0;
                if (tid < 256) { v = sfx[tid]; if (tid + off < 256) v += sfx[tid + off]; }
                __syncthreads();
                if (tid < 256) sfx[tid] = v;
                __syncthreads();
            }
            if (tid < 256) {
                int need = s_need;
                int hi = (tid == 255) ? 0 : sfx[tid + 1];
                if (sfx[tid] >= need && hi < need) {       // unique chosen bin
                    s_prefix = pfx | ((unsigned int)tid << shift);
                    s_need   = need - hi;
                }
            }
            __syncthreads();
        }
        filt = 1;
        kth  = inv_mono(s_prefix);   // exact value of the MAX_DET-th largest
    }

    // ---- scatter kept rows into the output ----
    for (int e = tid; e < count; e += 1024) {
        const float4 L0 = reinterpret_cast<const float4*>(g_list + (size_t)e*8)[0];
        const float4 L1 = reinterpret_cast<const float4*>(g_list + (size_t)e*8)[1];
        float s = L0.x;
        if (filt && !(s >= kth)) continue;
        int c = (int)L0.y;
        int j = (int)L0.z;
        int r = c*NROI + j;
        float* d = out + (size_t)r*6;
        d[0] = 0.0f;
        d[1] = L0.w;  // x1
        d[2] = L1.x;  // y1
        d[3] = L1.y;  // x2
        d[4] = L1.z;  // y2
        d[5] = s;
        out[NTOT*7 + r] = 1.0f;   // keep flag
    }

    // ---- restore invariant for the next invocation ----
    __syncthreads();
    if (tid == 0) g_kcount = 0;
}

extern "C" void kernel_launch(void* const* d_in, const int* in_sizes, int n_in,
                              void* d_out, int out_size) {
    const float* rois   = (const float*)d_in[0];
    const float* delta  = (const float*)d_in[1];
    const float* prob   = (const float*)d_in[2];
    const float* iminfo = (const float*)d_in[3];
    float* out = (float*)d_out;

    static_assert(sizeof(SMem) < 100*1024, "smem budget");
    cudaFuncSetAttribute(k_main, cudaFuncAttributeMaxDynamicSharedMemorySize,
                         (int)sizeof(SMem));

    k_main<<<NCLS, 256, sizeof(SMem)>>>(rois, delta, prob, iminfo, out);
    k_final<<<1, 1024>>>(out);
}